// round 13
// baseline (speedup 1.0000x reference)
#include <cuda_runtime.h>
#include <cuda_bf16.h>
#include <cstdint>
#include <math.h>

#define HH 192
#define WW 192
#define HW (192*192)
#define BB 4
#define DD 8

// ---------------------------------------------------------------------------
// Scratch (device globals — no allocation allowed)
// ---------------------------------------------------------------------------
__device__ float g_h [BB*8*HW];
__device__ float g_c [BB*8*HW];
__device__ float g_x0[BB*40*HW];
__device__ float g_x1[BB*40*HW];
__device__ float g_bnp[40*8*2];     // BN partials [c][slice][{sum,sumsq}]
// pixel-major packed bf16 hi/lo: [b][pix][80]  (ch 0..39 hi, 40..79 lo)
__device__ __align__(16) __nv_bfloat16 g_int[(size_t)BB*HW*80];
__device__ __align__(16) __nv_bfloat16 g_rt [(size_t)BB*HW*80];
__device__ __align__(16) __nv_bfloat16 g_x0t[(size_t)BB*HW*80];
__device__ __align__(16) __nv_bfloat16 g_x1t[(size_t)BB*HW*80];

__device__ float g_Wg [56*40*9];    // [oc][ic][tap]
__device__ float g_bg [56];
__device__ float g_Wh2[11*40*25];   // [oc][ic][tap] (Wh centered in 5x5 | W2)
__device__ float g_bh2[16];

// B operand images, lane-permuted: [tap][n][128] bf16; within each 16-k chunk
// the order is (2p,2p+1,2p+8,2p+9) for p=0..3 so one LDG.64 per lane-fragment.
__device__ __align__(16) __nv_bfloat16 g_Bg[ 9*64*128];
__device__ __align__(16) __nv_bfloat16 g_B0[25*48*128];
__device__ __align__(16) __nv_bfloat16 g_B1[25*48*128];
__device__ __align__(16) __nv_bfloat16 g_Bh[25*16*128];

__device__ __forceinline__ float sigm_(float x) { return 1.f / (1.f + expf(-x)); }

__device__ __forceinline__ uint32_t smem_u32(const void* p) {
    uint32_t a;
    asm("{ .reg .u64 t; cvta.to.shared.u64 t, %1; cvt.u32.u64 %0, t; }" : "=r"(a) : "l"(p));
    return a;
}
__device__ __forceinline__ void cp16(uint32_t sdst, const void* gsrc) {
    asm volatile("cp.async.ca.shared.global [%0], [%1], 16;" :: "r"(sdst), "l"(gsrc));
}
#define CP_COMMIT() asm volatile("cp.async.commit_group;" ::: "memory")
#define CP_WAIT0()  asm volatile("cp.async.wait_group 0;" ::: "memory")

#define LDSM4(r, addr)                                                          \
    asm volatile("ldmatrix.sync.aligned.m8n8.x4.shared.b16 {%0,%1,%2,%3}, [%4];"\
        : "=r"((r)[0]), "=r"((r)[1]), "=r"((r)[2]), "=r"((r)[3]) : "r"(addr))
#define MMA16816(d, a, b)                                                       \
    asm volatile("mma.sync.aligned.m16n8k16.row.col.f32.bf16.bf16.f32 "         \
        "{%0,%1,%2,%3}, {%4,%5,%6,%7}, {%8,%9}, {%0,%1,%2,%3};"                 \
        : "+f"((d)[0]), "+f"((d)[1]), "+f"((d)[2]), "+f"((d)[3])                \
        : "r"((a)[0]), "r"((a)[1]), "r"((a)[2]), "r"((a)[3]),                   \
          "r"((b)[0]), "r"((b)[1]))

__device__ __forceinline__ uint32_t pk2(float a, float b) {
    __nv_bfloat162 t = __floats2bfloat162_rn(a, b);
    return *(uint32_t*)&t;
}
// split 40 fp32 -> packed 80 bf16 (hi pairs then lo pairs), 10x uint4 store
__device__ __forceinline__ void store_packed(__nv_bfloat16* dst, const float* v) {
    uint32_t w[40];
    #pragma unroll
    for (int j = 0; j < 20; ++j) {
        float a0 = v[2*j], a1 = v[2*j+1];
        float h0 = __bfloat162float(__float2bfloat16(a0));
        float h1 = __bfloat162float(__float2bfloat16(a1));
        w[j]      = pk2(h0, h1);
        w[20 + j] = pk2(a0 - h0, a1 - h1);
    }
    uint4* o = (uint4*)dst;
    #pragma unroll
    for (int i = 0; i < 10; ++i)
        o[i] = make_uint4(w[4*i], w[4*i+1], w[4*i+2], w[4*i+3]);
}

// ---------------------------------------------------------------------------
// Setup kernels
// ---------------------------------------------------------------------------
__global__ void zero_state_kernel() {
    int i = blockIdx.x * blockDim.x + threadIdx.x;
    if (i < BB*8*HW) { g_h[i] = 0.f; g_c[i] = 0.f; }
}

__global__ void prep_weights_kernel(
    const float* __restrict__ Wf, const float* __restrict__ bf,
    const float* __restrict__ Wi, const float* __restrict__ bi,
    const float* __restrict__ Wc, const float* __restrict__ bc,
    const float* __restrict__ Wq, const float* __restrict__ bq,
    const float* __restrict__ Wh, const float* __restrict__ bh,
    const float* __restrict__ W2, const float* __restrict__ b2)
{
    int i = blockIdx.x * blockDim.x + threadIdx.x;
    if (i < 56*40*9) {
        int oc = i / 360, r = i % 360;
        float v;
        if      (oc < 8 ) v = Wf[ oc     *360 + r];
        else if (oc < 16) v = Wi[(oc-8 ) *360 + r];
        else if (oc < 24) v = Wc[(oc-16) *360 + r];
        else              v = Wq[(oc-24) *360 + r];
        g_Wg[i] = v;
    }
    if (i < 56)
        g_bg[i] = (i < 8) ? bf[i] : (i < 16) ? bi[i-8] : (i < 24) ? bc[i-16] : bq[i-24];
    if (i < 11*40*25) {
        int oc = i / 1000, r = i % 1000, c = r / 25, k = r % 25, ky = k / 5, kx = k % 5;
        float v = 0.f;
        if (oc < 8) {
            if (ky >= 1 && ky <= 3 && kx >= 1 && kx <= 3)
                v = Wh[((oc*40 + c)*3 + (ky-1))*3 + (kx-1)];
        } else {
            v = W2[(((oc-8)*40 + c)*5 + ky)*5 + kx];
        }
        g_Wh2[i] = v;
    }
    if (i < 16) g_bh2[i] = (i < 8) ? bh[i] : (i < 11) ? b2[i-8] : 0.f;
}

// B images, lane-permuted within each 16-k chunk.
// logical k: <40 -> Whi[k], 40-79 -> Whi[k-40], 80-119 -> Wlo, 120-127 -> 0
__global__ void prep_B_kernel(const float* __restrict__ W, __nv_bfloat16* __restrict__ dst,
                              int ntaps, int NPAD, int ocv)
{
    int i = blockIdx.x * blockDim.x + threadIdx.x;
    if (i >= ntaps * NPAD * 128) return;
    int k = i & 127, n = (i >> 7) % NPAD, tap = i / (128 * NPAD);
    float v = 0.f;
    if (k < 120 && n < ocv) {
        int c = k % 40;
        float w  = W[(n*40 + c)*ntaps + tap];
        float hi = __bfloat162float(__float2bfloat16(w));
        v = (k < 80) ? hi : (w - hi);
    }
    int ks = k >> 4, kk = k & 15;
    int off = ks*16 + ((kk >> 1) & 3)*4 + (kk & 1) + ((kk & 8) >> 2);
    dst[((size_t)(tap*NPAD + n))*128 + off] = __float2bfloat16(v);
}

// ---------------------------------------------------------------------------
// Input transforms -> packed pixel-major bf16 hi/lo
// ---------------------------------------------------------------------------
__global__ void transform_cat_kernel(const float* __restrict__ x, int t,
                                     __nv_bfloat16* __restrict__ dst)
{
    int i = blockIdx.x * blockDim.x + threadIdx.x;
    if (i >= BB*HW) return;
    int b = i / HW, p = i - b*HW;
    float v[40];
    const float* xb = x + ((size_t)(b*DD + t)*32)*HW + p;
    #pragma unroll
    for (int c = 0; c < 32; ++c) v[c] = __ldg(&xb[(size_t)c*HW]);
    const float* hb = g_h + ((size_t)b*8)*HW + p;
    #pragma unroll
    for (int c = 0; c < 8; ++c) v[32+c] = __ldg(&hb[(size_t)c*HW]);
    store_packed(dst + (size_t)i*80, v);
}

// BN partial sums: grid (40, 8); block (c, slice) sums its HW/8 slice over 4 batches.
__global__ void bn_partial_kernel(const float* __restrict__ x)
{
    const int c = blockIdx.x, s = blockIdx.y;
    float sum = 0.f, sq = 0.f;
    for (int b = 0; b < BB; ++b) {
        const float4* p = (const float4*)(x + ((size_t)b*40 + c)*HW) + s*(HW/32);
        for (int i = threadIdx.x; i < HW/32; i += blockDim.x) {
            float4 v = __ldg(&p[i]);
            sum += v.x + v.y + v.z + v.w;
            sq  += v.x*v.x + v.y*v.y + v.z*v.z + v.w*v.w;
        }
    }
    __shared__ float ss[8], qq[8];
    #pragma unroll
    for (int o = 16; o; o >>= 1) {
        sum += __shfl_xor_sync(~0u, sum, o);
        sq  += __shfl_xor_sync(~0u, sq,  o);
    }
    int lane = threadIdx.x & 31, w = threadIdx.x >> 5;
    if (!lane) { ss[w] = sum; qq[w] = sq; }
    __syncthreads();
    if (threadIdx.x == 0) {
        float S = 0.f, Q = 0.f;
        for (int j = 0; j < (int)(blockDim.x >> 5); ++j) { S += ss[j]; Q += qq[j]; }
        g_bnp[(c*8 + s)*2]     = S;
        g_bnp[(c*8 + s)*2 + 1] = Q;
    }
}

// BN(final reduce) + ReLU + split-pack. Each block redundantly folds the 320
// partials (deterministic fixed order) — no extra launch.
__global__ void transform_bn_kernel(const float* __restrict__ src,
                                    const float* __restrict__ gamma,
                                    const float* __restrict__ beta,
                                    __nv_bfloat16* __restrict__ dst)
{
    __shared__ float ssc[40], ssh[40];
    if (threadIdx.x < 40) {
        float S = 0.f, Q = 0.f;
        #pragma unroll
        for (int j = 0; j < 8; ++j) {
            S += g_bnp[(threadIdx.x*8 + j)*2];
            Q += g_bnp[(threadIdx.x*8 + j)*2 + 1];
        }
        const float Nn = (float)(BB*HW);
        float m  = S / Nn;
        float vv = Q / Nn - m*m;
        float sc = gamma[threadIdx.x] * rsqrtf(vv + 1e-5f);
        ssc[threadIdx.x] = sc;
        ssh[threadIdx.x] = beta[threadIdx.x] - m*sc;
    }
    __syncthreads();
    int i = blockIdx.x * blockDim.x + threadIdx.x;
    if (i >= BB*HW) return;
    int b = i / HW, p = i - b*HW;
    float v[40];
    const float* sb = src + ((size_t)b*40)*HW + p;
    #pragma unroll
    for (int c = 0; c < 40; ++c)
        v[c] = fmaxf(__ldg(&sb[(size_t)c*HW]) * ssc[c] + ssh[c], 0.f);
    store_packed(dst + (size_t)i*80, v);
}

// ---------------------------------------------------------------------------
// HMMA implicit-GEMM conv, resident-A variant.
// Tile = 32x4 pixels; patch (with halo) loaded ONCE into smem at 176B/pixel
// stride; each tap re-points ldmatrix by (dy*PW+dx)*176. B fragments read by
// LDG.64 straight from the lane-permuted global image (L2/L1-hot, no smem, no
// barriers in the mainloop). 8 warps = 4(M)x2(N). Epilogue via smem D tile.
// EPI: 0 = gate + fused LSTM (writes g_c + packed g_rt)
//      1 = planar fp32 out (po)
//      2 = head: h-state + depth output (pout, t)
// ---------------------------------------------------------------------------
template<int KD, int NPAD, int NREAL, int EPI>
__global__ __launch_bounds__(256)
void mma_conv_kernel(const __nv_bfloat16* __restrict__ inpk,
                     const __nv_bfloat16* __restrict__ Bsrc,
                     float* __restrict__ po, float* __restrict__ pout, int t)
{
    constexpr int T    = KD*KD;
    constexpr int PADK = KD/2;
    constexpr int PW   = 32 + KD - 1;
    constexpr int PH   = 4 + KD - 1;
    constexpr int NPIX = PH*PW;
    constexpr int BT   = NPAD/16;
    constexpr int DSTR = NPAD + 5;

    extern __shared__ __align__(16) char smem[];
    const uint32_t sA = smem_u32(smem);

    const int tid  = threadIdx.x;
    const int lane = tid & 31;
    const int wid  = tid >> 5;
    const int wm   = wid & 3;
    const int wn   = wid >> 2;
    const int mbase = wm*32;
    const int nbase = wn*(NPAD/2);

    const int b   = blockIdx.x / 288;
    const int rem = blockIdx.x - b*288;
    const int ty  = rem / 6, tx = rem - (rem/6)*6;
    const int y0  = ty*4,  x0 = tx*32;
    const size_t bpix = (size_t)b * HW;

    // ---- patch fill (once) ----
    {
        const char* base = (const char*)inpk;
        for (int u = tid; u < NPIX*2; u += 256) {
            int pix = u >> 1, half = u & 1;
            int pyy = pix / PW, pxx = pix - pyy*PW;
            int gy = y0 - PADK + pyy, gx = x0 - PADK + pxx;
            uint32_t dst = sA + pix*176 + half*80;
            if ((unsigned)gy < HH && (unsigned)gx < WW) {
                const char* src = base + ((size_t)(bpix + gy*WW + gx))*160 + half*80;
                #pragma unroll
                for (int j = 0; j < 5; ++j) cp16(dst + j*16, src + j*16);
            } else {
                #pragma unroll
                for (int j = 0; j < 5; ++j)
                    *(uint4*)(smem + pix*176 + half*80 + j*16) = make_uint4(0,0,0,0);
            }
        }
        CP_COMMIT();
        CP_WAIT0();
        __syncthreads();
    }

    // per-lane A fragment bases (row -> patch pixel)
    const int r0  = mbase + (lane & 15);
    const int yy  = r0 >> 5, xx = r0 & 31;
    const uint32_t aBase0 = sA + (uint32_t)(((yy + PADK)*PW + xx + PADK)*176)
                          + (uint32_t)((lane >> 4)*16);
    const uint32_t aBase1 = aBase0 + 16*176;

    float acc[2][BT][4];
    #pragma unroll
    for (int mt = 0; mt < 2; ++mt)
        #pragma unroll
        for (int j = 0; j < BT; ++j)
            #pragma unroll
            for (int q = 0; q < 4; ++q) acc[mt][j][q] = 0.f;

    const int G0[8] = {0, 2, 4, 6, 8, 0, 2, 4};   // A k-group aliasing table
    const char* Bb = (const char*)Bsrc;

    for (int tap = 0; tap < T; ++tap) {
        const int dy = tap / KD - PADK, dx = tap % KD - PADK;
        const uint32_t sh = (uint32_t)((dy*PW + dx)*176);
        const char* Bt = Bb + (size_t)tap*NPAD*256
                       + (nbase + (lane >> 2))*256 + (lane & 3)*8;
        #pragma unroll
        for (int ks = 0; ks < 8; ++ks) {
            uint32_t a0[4], a1[4];
            const uint32_t off = sh + G0[ks]*16;
            LDSM4(a0, aBase0 + off);
            LDSM4(a1, aBase1 + off);
            #pragma unroll
            for (int j = 0; j < BT; ++j) {
                uint2 bb = __ldg((const uint2*)(Bt + ks*32 + j*8*256));
                uint32_t b2[2] = {bb.x, bb.y};
                MMA16816(acc[0][j], a0, b2);
                MMA16816(acc[1][j], a1, b2);
            }
        }
    }

    __syncthreads();   // all A reads done before D-tile aliases smem

    // ---- write D fragments to smem D tile ----
    {
        float* sD = (float*)smem;
        int r = mbase + (lane >> 2);
        int c0 = nbase + 2*(lane & 3);
        #pragma unroll
        for (int mt = 0; mt < 2; ++mt) {
            #pragma unroll
            for (int j = 0; j < BT; ++j) {
                int rr = r + mt*16, cc = c0 + j*8;
                sD[(rr    )*DSTR + cc    ] = acc[mt][j][0];
                sD[(rr    )*DSTR + cc + 1] = acc[mt][j][1];
                sD[(rr + 8)*DSTR + cc    ] = acc[mt][j][2];
                sD[(rr + 8)*DSTR + cc + 1] = acc[mt][j][3];
            }
        }
    }
    __syncthreads();

    // ---- per-pixel epilogue (threads 0-127, thread = pixel) ----
    if (tid < 128) {
        const float* sD = (const float*)smem + tid*DSTR;
        const int pimg = (y0 + (tid >> 5))*WW + x0 + (tid & 31);
        if (EPI == 0) {
            float v[40];
            float* C = g_c + (size_t)b*8*HW + pimg;
            #pragma unroll
            for (int c = 0; c < 8; ++c) {
                float f  = sigm_(sD[c]      + g_bg[c]);
                float ii = sigm_(sD[8 + c]  + g_bg[8 + c]);
                float gg = tanhf(sD[16 + c] + g_bg[16 + c]);
                float cs = f * C[(size_t)c*HW] + ii * gg;
                C[(size_t)c*HW] = cs;
                v[c] = cs;
            }
            #pragma unroll
            for (int j = 0; j < 32; ++j) v[8+j] = sigm_(sD[24+j] + g_bg[24+j]);
            store_packed(g_rt + (bpix + pimg)*80, v);
        } else if (EPI == 1) {
            float* O = po + (size_t)b*40*HW + pimg;
            #pragma unroll
            for (int c = 0; c < 40; ++c) O[(size_t)c*HW] = sD[c];
        } else {
            float* Hh = g_h + (size_t)b*8*HW + pimg;
            #pragma unroll
            for (int c = 0; c < 8; ++c) Hh[(size_t)c*HW] = sD[c] + g_bh2[c];
            #pragma unroll
            for (int j = 0; j < 3; ++j)
                pout[(((size_t)b*3 + j)*DD + t)*HW + pimg] = sD[8+j] + g_bh2[8+j];
        }
    }
}

// ---------------------------------------------------------------------------
// Host driver
// ---------------------------------------------------------------------------
extern "C" void kernel_launch(void* const* d_in, const int* in_sizes, int n_in,
                              void* d_out, int out_size)
{
    const float* x1  = (const float*)d_in[0];
    const float* x2  = (const float*)d_in[1];
    const float* Wf  = (const float*)d_in[2];
    const float* bf  = (const float*)d_in[3];
    const float* Wi  = (const float*)d_in[4];
    const float* bi  = (const float*)d_in[5];
    const float* Wc  = (const float*)d_in[6];
    const float* bc  = (const float*)d_in[7];
    const float* Wq  = (const float*)d_in[8];
    const float* bq  = (const float*)d_in[9];
    const float* W0  = (const float*)d_in[10];
    const float* g0  = (const float*)d_in[11];
    const float* be0 = (const float*)d_in[12];
    const float* W1  = (const float*)d_in[13];
    const float* g1  = (const float*)d_in[14];
    const float* be1 = (const float*)d_in[15];
    const float* W2  = (const float*)d_in[16];
    const float* b2w = (const float*)d_in[17];
    const float* Wh  = (const float*)d_in[18];
    const float* bh  = (const float*)d_in[19];
    float* out = (float*)d_out;

    float *px0, *px1, *pWg, *pWh2;
    __nv_bfloat16 *pint, *prt, *px0t, *px1t, *pBg, *pB0, *pB1, *pBh;
    cudaGetSymbolAddress((void**)&px0,  g_x0);
    cudaGetSymbolAddress((void**)&px1,  g_x1);
    cudaGetSymbolAddress((void**)&pWg,  g_Wg);
    cudaGetSymbolAddress((void**)&pWh2, g_Wh2);
    cudaGetSymbolAddress((void**)&pint, g_int);
    cudaGetSymbolAddress((void**)&prt,  g_rt);
    cudaGetSymbolAddress((void**)&px0t, g_x0t);
    cudaGetSymbolAddress((void**)&px1t, g_x1t);
    cudaGetSymbolAddress((void**)&pBg,  g_Bg);
    cudaGetSymbolAddress((void**)&pB0,  g_B0);
    cudaGetSymbolAddress((void**)&pB1,  g_B1);
    cudaGetSymbolAddress((void**)&pBh,  g_Bh);

    // dynamic smem: max(patch, D tile)
    constexpr int SM_G = 35904;   // 3x3: patch 204*176=35904 > D 128*69*4
    constexpr int SM_C = 50688;   // 5x5: patch 288*176=50688
    constexpr int SM_H = 50688;
    cudaFuncSetAttribute(mma_conv_kernel<3,64,56,0>,
                         cudaFuncAttributeMaxDynamicSharedMemorySize, SM_G);
    cudaFuncSetAttribute(mma_conv_kernel<5,48,40,1>,
                         cudaFuncAttributeMaxDynamicSharedMemorySize, SM_C);
    cudaFuncSetAttribute(mma_conv_kernel<5,16,11,2>,
                         cudaFuncAttributeMaxDynamicSharedMemorySize, SM_H);

    zero_state_kernel<<<(BB*8*HW + 255)/256, 256>>>();
    prep_weights_kernel<<<(56*40*9 + 255)/256, 256>>>(Wf, bf, Wi, bi, Wc, bc, Wq, bq,
                                                      Wh, bh, W2, b2w);
    prep_B_kernel<<<( 9*64*128 + 255)/256, 256>>>(pWg,  pBg,  9, 64, 56);
    prep_B_kernel<<<(25*48*128 + 255)/256, 256>>>(W0,   pB0, 25, 48, 40);
    prep_B_kernel<<<(25*48*128 + 255)/256, 256>>>(W1,   pB1, 25, 48, 40);
    prep_B_kernel<<<(25*16*128 + 255)/256, 256>>>(pWh2, pBh, 25, 16, 11);

    const size_t O2_OFF = (size_t)BB*3*DD*HW;
    const int NT = 288*BB;              // 1152 tiles (6x * 48y * 4b)
    const int NP = (BB*HW + 255)/256;   // 576 pointwise blocks

    for (int t = 0; t < DD; ++t) {
        for (int phase = 0; phase < 2; ++phase) {
            const float* xin   = phase ? x2 : x1;
            float*       obase = out + (phase ? O2_OFF : 0);

            transform_cat_kernel<<<NP, 256>>>(xin, t, pint);

            // gate conv + fused LSTM -> g_c, packed g_rt
            mma_conv_kernel<3,64,56,0><<<NT, 256, SM_G>>>(pint, pBg, nullptr, nullptr, 0);

            // conv0 -> planar x0
            mma_conv_kernel<5,48,40,1><<<NT, 256, SM_C>>>(prt, pB0, px0, nullptr, 0);
            bn_partial_kernel<<<dim3(40, 8), 256>>>(px0);
            transform_bn_kernel<<<NP, 256>>>(px0, g0, be0, px0t);

            // conv1 -> planar x1
            mma_conv_kernel<5,48,40,1><<<NT, 256, SM_C>>>(px0t, pB1, px1, nullptr, 0);
            bn_partial_kernel<<<dim3(40, 8), 256>>>(px1);
            transform_bn_kernel<<<NP, 256>>>(px1, g1, be1, px1t);

            // head -> h-state + depth output
            mma_conv_kernel<5,16,11,2><<<NT, 256, SM_H>>>(px1t, pBh, nullptr, obase, t);
        }
    }
}

// round 14
// speedup vs baseline: 1.5463x; 1.5463x over previous
#include <cuda_runtime.h>
#include <cuda_bf16.h>
#include <cstdint>
#include <math.h>

#define HH 192
#define WW 192
#define HW (192*192)
#define BB 4
#define DD 8

// ---------------------------------------------------------------------------
// Scratch (device globals — no allocation allowed)
// ---------------------------------------------------------------------------
__device__ float g_h [BB*8*HW];
__device__ float g_c [BB*8*HW];
__device__ float g_x0[BB*40*HW];
__device__ float g_x1[BB*40*HW];
__device__ float g_bnp[40*8*2];     // BN partials [c][slice][{sum,sumsq}]
// pixel-major packed bf16 hi/lo: [b][pix][80]  (ch 0..39 hi, 40..79 lo)
__device__ __align__(16) __nv_bfloat16 g_int[(size_t)BB*HW*80];
__device__ __align__(16) __nv_bfloat16 g_rt [(size_t)BB*HW*80];
__device__ __align__(16) __nv_bfloat16 g_x0t[(size_t)BB*HW*80];
__device__ __align__(16) __nv_bfloat16 g_x1t[(size_t)BB*HW*80];

__device__ float g_Wg [56*40*9];    // [oc][ic][tap]
__device__ float g_bg [56];
__device__ float g_Wh2[11*40*25];   // [oc][ic][tap] (Wh centered in 5x5 | W2)
__device__ float g_bh2[16];

// B operand images (plain): [tap][n][128] bf16
// k: 0-39 Whi, 40-79 Whi (dup), 80-119 Wlo, 120-127 zero
__device__ __align__(16) __nv_bfloat16 g_Bg[ 9*64*128];
__device__ __align__(16) __nv_bfloat16 g_B0[25*48*128];
__device__ __align__(16) __nv_bfloat16 g_B1[25*48*128];
__device__ __align__(16) __nv_bfloat16 g_Bh[25*16*128];

__device__ __forceinline__ float sigm_(float x) { return 1.f / (1.f + expf(-x)); }

__device__ __forceinline__ uint32_t smem_u32(const void* p) {
    uint32_t a;
    asm("{ .reg .u64 t; cvta.to.shared.u64 t, %1; cvt.u32.u64 %0, t; }" : "=r"(a) : "l"(p));
    return a;
}
__device__ __forceinline__ void cp16(uint32_t sdst, const void* gsrc) {
    asm volatile("cp.async.ca.shared.global [%0], [%1], 16;" :: "r"(sdst), "l"(gsrc));
}
#define CP_COMMIT() asm volatile("cp.async.commit_group;" ::: "memory")
#define CP_WAIT1()  asm volatile("cp.async.wait_group 1;" ::: "memory")
#define CP_WAIT0()  asm volatile("cp.async.wait_group 0;" ::: "memory")

#define LDSM4(r, addr)                                                          \
    asm volatile("ldmatrix.sync.aligned.m8n8.x4.shared.b16 {%0,%1,%2,%3}, [%4];"\
        : "=r"((r)[0]), "=r"((r)[1]), "=r"((r)[2]), "=r"((r)[3]) : "r"(addr))
#define LDSM2(r, addr)                                                          \
    asm volatile("ldmatrix.sync.aligned.m8n8.x2.shared.b16 {%0,%1}, [%2];"      \
        : "=r"((r)[0]), "=r"((r)[1]) : "r"(addr))
#define MMA16816(d, a, b)                                                       \
    asm volatile("mma.sync.aligned.m16n8k16.row.col.f32.bf16.bf16.f32 "         \
        "{%0,%1,%2,%3}, {%4,%5,%6,%7}, {%8,%9}, {%0,%1,%2,%3};"                 \
        : "+f"((d)[0]), "+f"((d)[1]), "+f"((d)[2]), "+f"((d)[3])                \
        : "r"((a)[0]), "r"((a)[1]), "r"((a)[2]), "r"((a)[3]),                   \
          "r"((b)[0]), "r"((b)[1]))

__device__ __forceinline__ uint32_t pk2(float a, float b) {
    __nv_bfloat162 t = __floats2bfloat162_rn(a, b);
    return *(uint32_t*)&t;
}
// split 40 fp32 -> packed 80 bf16 (hi pairs then lo pairs), 10x uint4 store
__device__ __forceinline__ void store_packed(__nv_bfloat16* dst, const float* v) {
    uint32_t w[40];
    #pragma unroll
    for (int j = 0; j < 20; ++j) {
        float a0 = v[2*j], a1 = v[2*j+1];
        float h0 = __bfloat162float(__float2bfloat16(a0));
        float h1 = __bfloat162float(__float2bfloat16(a1));
        w[j]      = pk2(h0, h1);
        w[20 + j] = pk2(a0 - h0, a1 - h1);
    }
    uint4* o = (uint4*)dst;
    #pragma unroll
    for (int i = 0; i < 10; ++i)
        o[i] = make_uint4(w[4*i], w[4*i+1], w[4*i+2], w[4*i+3]);
}

// ---------------------------------------------------------------------------
// Setup kernels
// ---------------------------------------------------------------------------
__global__ void zero_state_kernel() {
    int i = blockIdx.x * blockDim.x + threadIdx.x;
    if (i < BB*8*HW) { g_h[i] = 0.f; g_c[i] = 0.f; }
}

__global__ void prep_weights_kernel(
    const float* __restrict__ Wf, const float* __restrict__ bf,
    const float* __restrict__ Wi, const float* __restrict__ bi,
    const float* __restrict__ Wc, const float* __restrict__ bc,
    const float* __restrict__ Wq, const float* __restrict__ bq,
    const float* __restrict__ Wh, const float* __restrict__ bh,
    const float* __restrict__ W2, const float* __restrict__ b2)
{
    int i = blockIdx.x * blockDim.x + threadIdx.x;
    if (i < 56*40*9) {
        int oc = i / 360, r = i % 360;
        float v;
        if      (oc < 8 ) v = Wf[ oc     *360 + r];
        else if (oc < 16) v = Wi[(oc-8 ) *360 + r];
        else if (oc < 24) v = Wc[(oc-16) *360 + r];
        else              v = Wq[(oc-24) *360 + r];
        g_Wg[i] = v;
    }
    if (i < 56)
        g_bg[i] = (i < 8) ? bf[i] : (i < 16) ? bi[i-8] : (i < 24) ? bc[i-16] : bq[i-24];
    if (i < 11*40*25) {
        int oc = i / 1000, r = i % 1000, c = r / 25, k = r % 25, ky = k / 5, kx = k % 5;
        float v = 0.f;
        if (oc < 8) {
            if (ky >= 1 && ky <= 3 && kx >= 1 && kx <= 3)
                v = Wh[((oc*40 + c)*3 + (ky-1))*3 + (kx-1)];
        } else {
            v = W2[(((oc-8)*40 + c)*5 + ky)*5 + kx];
        }
        g_Wh2[i] = v;
    }
    if (i < 16) g_bh2[i] = (i < 8) ? bh[i] : (i < 11) ? b2[i-8] : 0.f;
}

// B images (plain layout, R10-validated):
// logical k: <40 -> Whi[k], 40-79 -> Whi[k-40], 80-119 -> Wlo, 120-127 -> 0
__global__ void prep_B_kernel(const float* __restrict__ W, __nv_bfloat16* __restrict__ dst,
                              int ntaps, int NPAD, int ocv)
{
    int i = blockIdx.x * blockDim.x + threadIdx.x;
    if (i >= ntaps * NPAD * 128) return;
    int k = i & 127, n = (i >> 7) % NPAD, tap = i / (128 * NPAD);
    float v = 0.f;
    if (k < 120 && n < ocv) {
        int c = k % 40;
        float w  = W[(n*40 + c)*ntaps + tap];
        float hi = __bfloat162float(__float2bfloat16(w));
        v = (k < 80) ? hi : (w - hi);
    }
    dst[i] = __float2bfloat16(v);
}

// ---------------------------------------------------------------------------
// Input transforms -> packed pixel-major bf16 hi/lo
// ---------------------------------------------------------------------------
__global__ void transform_cat_kernel(const float* __restrict__ x, int t,
                                     __nv_bfloat16* __restrict__ dst)
{
    int i = blockIdx.x * blockDim.x + threadIdx.x;
    if (i >= BB*HW) return;
    int b = i / HW, p = i - b*HW;
    float v[40];
    const float* xb = x + ((size_t)(b*DD + t)*32)*HW + p;
    #pragma unroll
    for (int c = 0; c < 32; ++c) v[c] = __ldg(&xb[(size_t)c*HW]);
    const float* hb = g_h + ((size_t)b*8)*HW + p;
    #pragma unroll
    for (int c = 0; c < 8; ++c) v[32+c] = __ldg(&hb[(size_t)c*HW]);
    store_packed(dst + (size_t)i*80, v);
}

// BN partial sums: grid (40, 8); block (c, slice) sums its HW/8 slice over 4 batches.
__global__ void bn_partial_kernel(const float* __restrict__ x)
{
    const int c = blockIdx.x, s = blockIdx.y;
    float sum = 0.f, sq = 0.f;
    for (int b = 0; b < BB; ++b) {
        const float4* p = (const float4*)(x + ((size_t)b*40 + c)*HW) + s*(HW/32);
        for (int i = threadIdx.x; i < HW/32; i += blockDim.x) {
            float4 v = __ldg(&p[i]);
            sum += v.x + v.y + v.z + v.w;
            sq  += v.x*v.x + v.y*v.y + v.z*v.z + v.w*v.w;
        }
    }
    __shared__ float ss[8], qq[8];
    #pragma unroll
    for (int o = 16; o; o >>= 1) {
        sum += __shfl_xor_sync(~0u, sum, o);
        sq  += __shfl_xor_sync(~0u, sq,  o);
    }
    int lane = threadIdx.x & 31, w = threadIdx.x >> 5;
    if (!lane) { ss[w] = sum; qq[w] = sq; }
    __syncthreads();
    if (threadIdx.x == 0) {
        float S = 0.f, Q = 0.f;
        for (int j = 0; j < (int)(blockDim.x >> 5); ++j) { S += ss[j]; Q += qq[j]; }
        g_bnp[(c*8 + s)*2]     = S;
        g_bnp[(c*8 + s)*2 + 1] = Q;
    }
}

// BN(final reduce) + ReLU + split-pack. Each block redundantly folds the
// partials (deterministic fixed order) — no extra launch.
__global__ void transform_bn_kernel(const float* __restrict__ src,
                                    const float* __restrict__ gamma,
                                    const float* __restrict__ beta,
                                    __nv_bfloat16* __restrict__ dst)
{
    __shared__ float ssc[40], ssh[40];
    if (threadIdx.x < 40) {
        float S = 0.f, Q = 0.f;
        #pragma unroll
        for (int j = 0; j < 8; ++j) {
            S += g_bnp[(threadIdx.x*8 + j)*2];
            Q += g_bnp[(threadIdx.x*8 + j)*2 + 1];
        }
        const float Nn = (float)(BB*HW);
        float m  = S / Nn;
        float vv = Q / Nn - m*m;
        float sc = gamma[threadIdx.x] * rsqrtf(vv + 1e-5f);
        ssc[threadIdx.x] = sc;
        ssh[threadIdx.x] = beta[threadIdx.x] - m*sc;
    }
    __syncthreads();
    int i = blockIdx.x * blockDim.x + threadIdx.x;
    if (i >= BB*HW) return;
    int b = i / HW, p = i - b*HW;
    float v[40];
    const float* sb = src + ((size_t)b*40)*HW + p;
    #pragma unroll
    for (int c = 0; c < 40; ++c)
        v[c] = fmaxf(__ldg(&sb[(size_t)c*HW]) * ssc[c] + ssh[c], 0.f);
    store_packed(dst + (size_t)i*80, v);
}

// ---------------------------------------------------------------------------
// HMMA implicit-GEMM conv: resident-A patch + double-buffered smem B (LDSM).
// Tile = 32x4 pixels; patch (with halo) loaded ONCE at 176B/pixel stride;
// each tap re-points ldmatrix by (dy*PW+dx)*176 (bank-conflict-free: stride
// 176 -> 12-bank rotation per row). B per tap prefetched via cp.async into
// a 2-deep smem ring (272B rows, LDSM2). 8 warps = 4(M)x2(N).
// EPI: 0 = gate + fused LSTM (writes g_c + packed g_rt)
//      1 = planar fp32 out (po)
//      2 = head: h-state + depth output (pout, t)
// ---------------------------------------------------------------------------
template<int KD, int NPAD, int NREAL, int EPI>
__global__ __launch_bounds__(256)
void mma_conv_kernel(const __nv_bfloat16* __restrict__ inpk,
                     const __nv_bfloat16* __restrict__ Bsrc,
                     float* __restrict__ po, float* __restrict__ pout, int t)
{
    constexpr int T    = KD*KD;
    constexpr int PADK = KD/2;
    constexpr int PW   = 32 + KD - 1;
    constexpr int PH   = 4 + KD - 1;
    constexpr int NPIX = PH*PW;
    constexpr int BT   = NPAD/16;
    constexpr int DSTR = NPAD + 5;
    constexpr int PATCH = NPIX*176;
    constexpr int BROW = 272;
    constexpr int BSZ  = NPAD*BROW;

    extern __shared__ __align__(16) char smem[];
    const uint32_t sA  = smem_u32(smem);
    const uint32_t sBB = sA + PATCH;

    const int tid  = threadIdx.x;
    const int lane = tid & 31;
    const int wid  = tid >> 5;
    const int wm   = wid & 3;
    const int wn   = wid >> 2;
    const int mbase = wm*32;
    const int nbase = wn*(NPAD/2);

    const int b   = blockIdx.x / 288;
    const int rem = blockIdx.x - b*288;
    const int ty  = rem / 6, tx = rem - (rem/6)*6;
    const int y0  = ty*4,  x0 = tx*32;
    const size_t bpix = (size_t)b * HW;

    // ---- patch fill (once) ----
    {
        const char* base = (const char*)inpk;
        for (int u = tid; u < NPIX*2; u += 256) {
            int pix = u >> 1, half = u & 1;
            int pyy = pix / PW, pxx = pix - pyy*PW;
            int gy = y0 - PADK + pyy, gx = x0 - PADK + pxx;
            uint32_t dst = sA + pix*176 + half*80;
            if ((unsigned)gy < HH && (unsigned)gx < WW) {
                const char* src = base + ((size_t)(bpix + gy*WW + gx))*160 + half*80;
                #pragma unroll
                for (int j = 0; j < 5; ++j) cp16(dst + j*16, src + j*16);
            } else {
                #pragma unroll
                for (int j = 0; j < 5; ++j)
                    *(uint4*)(smem + pix*176 + half*80 + j*16) = make_uint4(0,0,0,0);
            }
        }
        CP_COMMIT();
    }

    // ---- B prefetch for tap 0 ----
    auto copyB = [&](int tp) {
        const char* src = (const char*)Bsrc + (size_t)tp*NPAD*256;
        uint32_t dst = sBB + (uint32_t)(tp & 1)*BSZ;
        #pragma unroll 4
        for (int idx = tid; idx < NPAD*16; idx += 256)
            cp16(dst + (idx >> 4)*BROW + (idx & 15)*16, src + idx*16);
        CP_COMMIT();
    };
    copyB(0);
    CP_WAIT0();
    __syncthreads();

    // per-lane A fragment bases (row -> patch pixel)
    const int r0  = mbase + (lane & 15);
    const int yy  = r0 >> 5, xx = r0 & 31;
    const uint32_t aBase0 = sA + (uint32_t)(((yy + PADK)*PW + xx + PADK)*176)
                          + (uint32_t)((lane >> 4)*16);
    const uint32_t aBase1 = aBase0 + 16*176;

    float acc[2][BT][4];
    #pragma unroll
    for (int mt = 0; mt < 2; ++mt)
        #pragma unroll
        for (int j = 0; j < BT; ++j)
            #pragma unroll
            for (int q = 0; q < 4; ++q) acc[mt][j][q] = 0.f;

    const int G0[8] = {0, 2, 4, 6, 8, 0, 2, 4};   // A k-group aliasing table

    for (int tap = 0; tap < T; ++tap) {
        // prefetch next B (other buffer; its last readers sync'd at end of tap-1)
        if (tap + 1 < T) { copyB(tap + 1); CP_WAIT1(); }
        else             { CP_WAIT0(); }
        __syncthreads();          // B(tap) visible to all warps

        const int dy = tap / KD - PADK, dx = tap % KD - PADK;
        const uint32_t sh = (uint32_t)((dy*PW + dx)*176);
        const uint32_t bB = sBB + (uint32_t)(tap & 1)*BSZ;
        const uint32_t rbBase = bB + (uint32_t)((nbase + (lane & 7))*BROW)
                              + (uint32_t)((lane >> 3) & 1)*16;
        #pragma unroll
        for (int ks = 0; ks < 8; ++ks) {
            uint32_t a0[4], a1[4];
            const uint32_t off = sh + G0[ks]*16;
            LDSM4(a0, aBase0 + off);
            LDSM4(a1, aBase1 + off);
            #pragma unroll
            for (int j = 0; j < BT; ++j) {
                uint32_t b2[2];
                LDSM2(b2, rbBase + ks*32 + j*8*BROW);
                MMA16816(acc[0][j], a0, b2);
                MMA16816(acc[1][j], a1, b2);
            }
        }
        __syncthreads();          // B(tap) reads done before tap+2 overwrites
    }

    // ---- write D fragments to smem D tile (aliases patch region) ----
    {
        float* sD = (float*)smem;
        int r = mbase + (lane >> 2);
        int c0 = nbase + 2*(lane & 3);
        #pragma unroll
        for (int mt = 0; mt < 2; ++mt) {
            #pragma unroll
            for (int j = 0; j < BT; ++j) {
                int rr = r + mt*16, cc = c0 + j*8;
                sD[(rr    )*DSTR + cc    ] = acc[mt][j][0];
                sD[(rr    )*DSTR + cc + 1] = acc[mt][j][1];
                sD[(rr + 8)*DSTR + cc    ] = acc[mt][j][2];
                sD[(rr + 8)*DSTR + cc + 1] = acc[mt][j][3];
            }
        }
    }
    __syncthreads();

    // ---- per-pixel epilogue (threads 0-127, thread = pixel) ----
    if (tid < 128) {
        const float* sD = (const float*)smem + tid*DSTR;
        const int pimg = (y0 + (tid >> 5))*WW + x0 + (tid & 31);
        if (EPI == 0) {
            float v[40];
            float* C = g_c + (size_t)b*8*HW + pimg;
            #pragma unroll
            for (int c = 0; c < 8; ++c) {
                float f  = sigm_(sD[c]      + g_bg[c]);
                float ii = sigm_(sD[8 + c]  + g_bg[8 + c]);
                float gg = tanhf(sD[16 + c] + g_bg[16 + c]);
                float cs = f * C[(size_t)c*HW] + ii * gg;
                C[(size_t)c*HW] = cs;
                v[c] = cs;
            }
            #pragma unroll
            for (int j = 0; j < 32; ++j) v[8+j] = sigm_(sD[24+j] + g_bg[24+j]);
            store_packed(g_rt + (bpix + pimg)*80, v);
        } else if (EPI == 1) {
            float* O = po + (size_t)b*40*HW + pimg;
            #pragma unroll
            for (int c = 0; c < 40; ++c) O[(size_t)c*HW] = sD[c];
        } else {
            float* Hh = g_h + (size_t)b*8*HW + pimg;
            #pragma unroll
            for (int c = 0; c < 8; ++c) Hh[(size_t)c*HW] = sD[c] + g_bh2[c];
            #pragma unroll
            for (int j = 0; j < 3; ++j)
                pout[(((size_t)b*3 + j)*DD + t)*HW + pimg] = sD[8+j] + g_bh2[8+j];
        }
    }
}

// ---------------------------------------------------------------------------
// Host driver
// ---------------------------------------------------------------------------
extern "C" void kernel_launch(void* const* d_in, const int* in_sizes, int n_in,
                              void* d_out, int out_size)
{
    const float* x1  = (const float*)d_in[0];
    const float* x2  = (const float*)d_in[1];
    const float* Wf  = (const float*)d_in[2];
    const float* bf  = (const float*)d_in[3];
    const float* Wi  = (const float*)d_in[4];
    const float* bi  = (const float*)d_in[5];
    const float* Wc  = (const float*)d_in[6];
    const float* bc  = (const float*)d_in[7];
    const float* Wq  = (const float*)d_in[8];
    const float* bq  = (const float*)d_in[9];
    const float* W0  = (const float*)d_in[10];
    const float* g0  = (const float*)d_in[11];
    const float* be0 = (const float*)d_in[12];
    const float* W1  = (const float*)d_in[13];
    const float* g1  = (const float*)d_in[14];
    const float* be1 = (const float*)d_in[15];
    const float* W2  = (const float*)d_in[16];
    const float* b2w = (const float*)d_in[17];
    const float* Wh  = (const float*)d_in[18];
    const float* bh  = (const float*)d_in[19];
    float* out = (float*)d_out;

    float *px0, *px1, *pWg, *pWh2;
    __nv_bfloat16 *pint, *prt, *px0t, *px1t, *pBg, *pB0, *pB1, *pBh;
    cudaGetSymbolAddress((void**)&px0,  g_x0);
    cudaGetSymbolAddress((void**)&px1,  g_x1);
    cudaGetSymbolAddress((void**)&pWg,  g_Wg);
    cudaGetSymbolAddress((void**)&pWh2, g_Wh2);
    cudaGetSymbolAddress((void**)&pint, g_int);
    cudaGetSymbolAddress((void**)&prt,  g_rt);
    cudaGetSymbolAddress((void**)&px0t, g_x0t);
    cudaGetSymbolAddress((void**)&px1t, g_x1t);
    cudaGetSymbolAddress((void**)&pBg,  g_Bg);
    cudaGetSymbolAddress((void**)&pB0,  g_B0);
    cudaGetSymbolAddress((void**)&pB1,  g_B1);
    cudaGetSymbolAddress((void**)&pBh,  g_Bh);

    // dynamic smem: patch + 2 B buffers (D tile aliases patch region)
    constexpr int SM_G = 204*176 + 2*64*272;   // 35904 + 34816 = 70720
    constexpr int SM_C = 288*176 + 2*48*272;   // 50688 + 26112 = 76800
    constexpr int SM_H = 288*176 + 2*16*272;   // 50688 +  8704 = 59392
    cudaFuncSetAttribute(mma_conv_kernel<3,64,56,0>,
                         cudaFuncAttributeMaxDynamicSharedMemorySize, SM_G);
    cudaFuncSetAttribute(mma_conv_kernel<5,48,40,1>,
                         cudaFuncAttributeMaxDynamicSharedMemorySize, SM_C);
    cudaFuncSetAttribute(mma_conv_kernel<5,16,11,2>,
                         cudaFuncAttributeMaxDynamicSharedMemorySize, SM_H);

    zero_state_kernel<<<(BB*8*HW + 255)/256, 256>>>();
    prep_weights_kernel<<<(56*40*9 + 255)/256, 256>>>(Wf, bf, Wi, bi, Wc, bc, Wq, bq,
                                                      Wh, bh, W2, b2w);
    prep_B_kernel<<<( 9*64*128 + 255)/256, 256>>>(pWg,  pBg,  9, 64, 56);
    prep_B_kernel<<<(25*48*128 + 255)/256, 256>>>(W0,   pB0, 25, 48, 40);
    prep_B_kernel<<<(25*48*128 + 255)/256, 256>>>(W1,   pB1, 25, 48, 40);
    prep_B_kernel<<<(25*16*128 + 255)/256, 256>>>(pWh2, pBh, 25, 16, 11);

    const size_t O2_OFF = (size_t)BB*3*DD*HW;
    const int NT = 288*BB;              // 1152 tiles (6x * 48y * 4b)
    const int NP = (BB*HW + 255)/256;   // 576 pointwise blocks

    for (int t = 0; t < DD; ++t) {
        for (int phase = 0; phase < 2; ++phase) {
            const float* xin   = phase ? x2 : x1;
            float*       obase = out + (phase ? O2_OFF : 0);

            transform_cat_kernel<<<NP, 256>>>(xin, t, pint);

            // gate conv + fused LSTM -> g_c, packed g_rt
            mma_conv_kernel<3,64,56,0><<<NT, 256, SM_G>>>(pint, pBg, nullptr, nullptr, 0);

            // conv0 -> planar x0
            mma_conv_kernel<5,48,40,1><<<NT, 256, SM_C>>>(prt, pB0, px0, nullptr, 0);
            bn_partial_kernel<<<dim3(40, 8), 256>>>(px0);
            transform_bn_kernel<<<NP, 256>>>(px0, g0, be0, px0t);

            // conv1 -> planar x1
            mma_conv_kernel<5,48,40,1><<<NT, 256, SM_C>>>(px0t, pB1, px1, nullptr, 0);
            bn_partial_kernel<<<dim3(40, 8), 256>>>(px1);
            transform_bn_kernel<<<NP, 256>>>(px1, g1, be1, px1t);

            // head -> h-state + depth output
            mma_conv_kernel<5,16,11,2><<<NT, 256, SM_H>>>(px1t, pBh, nullptr, obase, t);
        }
    }
}

// round 16
// speedup vs baseline: 1.5990x; 1.0341x over previous
#include <cuda_runtime.h>
#include <cuda_bf16.h>
#include <cstdint>
#include <math.h>

#define HH 192
#define WW 192
#define HW (192*192)
#define BB 4
#define DD 8

// ---------------------------------------------------------------------------
// Scratch (device globals — no allocation allowed)
// ---------------------------------------------------------------------------
__device__ float g_h [BB*8*HW];
__device__ float g_c [BB*8*HW];
__device__ float g_x0[BB*40*HW];
__device__ float g_x1[BB*40*HW];
__device__ float g_bnp[40*8*2];     // BN partials [c][slice][{sum,sumsq}]
// pixel-major packed bf16 hi/lo: [b][pix][80]  (ch 0..39 hi, 40..79 lo)
__device__ __align__(16) __nv_bfloat16 g_int[(size_t)BB*HW*80];
__device__ __align__(16) __nv_bfloat16 g_rt [(size_t)BB*HW*80];
__device__ __align__(16) __nv_bfloat16 g_x0t[(size_t)BB*HW*80];
__device__ __align__(16) __nv_bfloat16 g_x1t[(size_t)BB*HW*80];

__device__ float g_Wg [56*40*9];    // [oc][ic][tap]
__device__ float g_bg [56];
__device__ float g_Wh2[11*40*25];   // [oc][ic][tap] (Wh centered in 5x5 | W2)
__device__ float g_bh2[16];

// B operand images (plain): [tap][n][128] bf16
// k: 0-39 Whi, 40-79 Whi (dup), 80-119 Wlo, 120-127 zero
__device__ __align__(16) __nv_bfloat16 g_Bg[ 9*64*128];
__device__ __align__(16) __nv_bfloat16 g_B0[25*48*128];
__device__ __align__(16) __nv_bfloat16 g_B1[25*48*128];
__device__ __align__(16) __nv_bfloat16 g_Bh[25*16*128];

__device__ __forceinline__ float sigm_(float x) { return 1.f / (1.f + expf(-x)); }

__device__ __forceinline__ uint32_t smem_u32(const void* p) {
    uint32_t a;
    asm("{ .reg .u64 t; cvta.to.shared.u64 t, %1; cvt.u32.u64 %0, t; }" : "=r"(a) : "l"(p));
    return a;
}
__device__ __forceinline__ void cp16(uint32_t sdst, const void* gsrc) {
    asm volatile("cp.async.ca.shared.global [%0], [%1], 16;" :: "r"(sdst), "l"(gsrc));
}
#define CP_COMMIT() asm volatile("cp.async.commit_group;" ::: "memory")
#define CP_WAIT1()  asm volatile("cp.async.wait_group 1;" ::: "memory")
#define CP_WAIT0()  asm volatile("cp.async.wait_group 0;" ::: "memory")

#define LDSM4(r, addr)                                                          \
    asm volatile("ldmatrix.sync.aligned.m8n8.x4.shared.b16 {%0,%1,%2,%3}, [%4];"\
        : "=r"((r)[0]), "=r"((r)[1]), "=r"((r)[2]), "=r"((r)[3]) : "r"(addr))
#define LDSM2(r, addr)                                                          \
    asm volatile("ldmatrix.sync.aligned.m8n8.x2.shared.b16 {%0,%1}, [%2];"      \
        : "=r"((r)[0]), "=r"((r)[1]) : "r"(addr))
#define MMA16816(d, a, b)                                                       \
    asm volatile("mma.sync.aligned.m16n8k16.row.col.f32.bf16.bf16.f32 "         \
        "{%0,%1,%2,%3}, {%4,%5,%6,%7}, {%8,%9}, {%0,%1,%2,%3};"                 \
        : "+f"((d)[0]), "+f"((d)[1]), "+f"((d)[2]), "+f"((d)[3])                \
        : "r"((a)[0]), "r"((a)[1]), "r"((a)[2]), "r"((a)[3]),                   \
          "r"((b)[0]), "r"((b)[1]))

__device__ __forceinline__ uint32_t pk2(float a, float b) {
    __nv_bfloat162 t = __floats2bfloat162_rn(a, b);
    return *(uint32_t*)&t;
}
// split 40 fp32 -> packed 80 bf16 (hi pairs then lo pairs), 10x uint4 store
__device__ __forceinline__ void store_packed(__nv_bfloat16* dst, const float* v) {
    uint32_t w[40];
    #pragma unroll
    for (int j = 0; j < 20; ++j) {
        float a0 = v[2*j], a1 = v[2*j+1];
        float h0 = __bfloat162float(__float2bfloat16(a0));
        float h1 = __bfloat162float(__float2bfloat16(a1));
        w[j]      = pk2(h0, h1);
        w[20 + j] = pk2(a0 - h0, a1 - h1);
    }
    uint4* o = (uint4*)dst;
    #pragma unroll
    for (int i = 0; i < 10; ++i)
        o[i] = make_uint4(w[4*i], w[4*i+1], w[4*i+2], w[4*i+3]);
}

// ---------------------------------------------------------------------------
// Setup kernels
// ---------------------------------------------------------------------------
__global__ void zero_state_kernel() {
    int i = blockIdx.x * blockDim.x + threadIdx.x;
    if (i < BB*8*HW) { g_h[i] = 0.f; g_c[i] = 0.f; }
}

__global__ void prep_weights_kernel(
    const float* __restrict__ Wf, const float* __restrict__ bf,
    const float* __restrict__ Wi, const float* __restrict__ bi,
    const float* __restrict__ Wc, const float* __restrict__ bc,
    const float* __restrict__ Wq, const float* __restrict__ bq,
    const float* __restrict__ Wh, const float* __restrict__ bh,
    const float* __restrict__ W2, const float* __restrict__ b2)
{
    int i = blockIdx.x * blockDim.x + threadIdx.x;
    if (i < 56*40*9) {
        int oc = i / 360, r = i % 360;
        float v;
        if      (oc < 8 ) v = Wf[ oc     *360 + r];
        else if (oc < 16) v = Wi[(oc-8 ) *360 + r];
        else if (oc < 24) v = Wc[(oc-16) *360 + r];
        else              v = Wq[(oc-24) *360 + r];
        g_Wg[i] = v;
    }
    if (i < 56)
        g_bg[i] = (i < 8) ? bf[i] : (i < 16) ? bi[i-8] : (i < 24) ? bc[i-16] : bq[i-24];
    if (i < 11*40*25) {
        int oc = i / 1000, r = i % 1000, c = r / 25, k = r % 25, ky = k / 5, kx = k % 5;
        float v = 0.f;
        if (oc < 8) {
            if (ky >= 1 && ky <= 3 && kx >= 1 && kx <= 3)
                v = Wh[((oc*40 + c)*3 + (ky-1))*3 + (kx-1)];
        } else {
            v = W2[(((oc-8)*40 + c)*5 + ky)*5 + kx];
        }
        g_Wh2[i] = v;
    }
    if (i < 16) g_bh2[i] = (i < 8) ? bh[i] : (i < 11) ? b2[i-8] : 0.f;
}

// B images (plain layout, R10-validated):
// logical k: <40 -> Whi[k], 40-79 -> Whi[k-40], 80-119 -> Wlo, 120-127 -> 0
__global__ void prep_B_kernel(const float* __restrict__ W, __nv_bfloat16* __restrict__ dst,
                              int ntaps, int NPAD, int ocv)
{
    int i = blockIdx.x * blockDim.x + threadIdx.x;
    if (i >= ntaps * NPAD * 128) return;
    int k = i & 127, n = (i >> 7) % NPAD, tap = i / (128 * NPAD);
    float v = 0.f;
    if (k < 120 && n < ocv) {
        int c = k % 40;
        float w  = W[(n*40 + c)*ntaps + tap];
        float hi = __bfloat162float(__float2bfloat16(w));
        v = (k < 80) ? hi : (w - hi);
    }
    dst[i] = __float2bfloat16(v);
}

// ---------------------------------------------------------------------------
// Input transforms -> packed pixel-major bf16 hi/lo
// ---------------------------------------------------------------------------
__global__ void transform_cat_kernel(const float* __restrict__ x, int t,
                                     __nv_bfloat16* __restrict__ dst)
{
    int i = blockIdx.x * blockDim.x + threadIdx.x;
    if (i >= BB*HW) return;
    int b = i / HW, p = i - b*HW;
    float v[40];
    const float* xb = x + ((size_t)(b*DD + t)*32)*HW + p;
    #pragma unroll
    for (int c = 0; c < 32; ++c) v[c] = __ldg(&xb[(size_t)c*HW]);
    const float* hb = g_h + ((size_t)b*8)*HW + p;
    #pragma unroll
    for (int c = 0; c < 8; ++c) v[32+c] = __ldg(&hb[(size_t)c*HW]);
    store_packed(dst + (size_t)i*80, v);
}

// BN partial sums: grid (40, 8); block (c, slice) sums its HW/8 slice over 4 batches.
__global__ void bn_partial_kernel(const float* __restrict__ x)
{
    const int c = blockIdx.x, s = blockIdx.y;
    float sum = 0.f, sq = 0.f;
    for (int b = 0; b < BB; ++b) {
        const float4* p = (const float4*)(x + ((size_t)b*40 + c)*HW) + s*(HW/32);
        for (int i = threadIdx.x; i < HW/32; i += blockDim.x) {
            float4 v = __ldg(&p[i]);
            sum += v.x + v.y + v.z + v.w;
            sq  += v.x*v.x + v.y*v.y + v.z*v.z + v.w*v.w;
        }
    }
    __shared__ float ss[8], qq[8];
    #pragma unroll
    for (int o = 16; o; o >>= 1) {
        sum += __shfl_xor_sync(~0u, sum, o);
        sq  += __shfl_xor_sync(~0u, sq,  o);
    }
    int lane = threadIdx.x & 31, w = threadIdx.x >> 5;
    if (!lane) { ss[w] = sum; qq[w] = sq; }
    __syncthreads();
    if (threadIdx.x == 0) {
        float S = 0.f, Q = 0.f;
        for (int j = 0; j < (int)(blockDim.x >> 5); ++j) { S += ss[j]; Q += qq[j]; }
        g_bnp[(c*8 + s)*2]     = S;
        g_bnp[(c*8 + s)*2 + 1] = Q;
    }
}

// BN(final reduce) + ReLU + split-pack. Each block redundantly folds the
// partials (deterministic fixed order) — no extra launch.
__global__ void transform_bn_kernel(const float* __restrict__ src,
                                    const float* __restrict__ gamma,
                                    const float* __restrict__ beta,
                                    __nv_bfloat16* __restrict__ dst)
{
    __shared__ float ssc[40], ssh[40];
    if (threadIdx.x < 40) {
        float S = 0.f, Q = 0.f;
        #pragma unroll
        for (int j = 0; j < 8; ++j) {
            S += g_bnp[(threadIdx.x*8 + j)*2];
            Q += g_bnp[(threadIdx.x*8 + j)*2 + 1];
        }
        const float Nn = (float)(BB*HW);
        float m  = S / Nn;
        float vv = Q / Nn - m*m;
        float sc = gamma[threadIdx.x] * rsqrtf(vv + 1e-5f);
        ssc[threadIdx.x] = sc;
        ssh[threadIdx.x] = beta[threadIdx.x] - m*sc;
    }
    __syncthreads();
    int i = blockIdx.x * blockDim.x + threadIdx.x;
    if (i >= BB*HW) return;
    int b = i / HW, p = i - b*HW;
    float v[40];
    const float* sb = src + ((size_t)b*40)*HW + p;
    #pragma unroll
    for (int c = 0; c < 40; ++c)
        v[c] = fmaxf(__ldg(&sb[(size_t)c*HW]) * ssc[c] + ssh[c], 0.f);
    store_packed(dst + (size_t)i*80, v);
}

// ---------------------------------------------------------------------------
// HMMA implicit-GEMM conv: resident-A patch + double-buffered smem B (LDSM).
// Tile = 16x8 pixels (square-ish: minimal halo -> smem fits 3 blocks/SM).
// Patch loaded ONCE at 176B/pixel stride; each tap re-points ldmatrix by
// (dy*PW+dx)*176 (conflict-free: 176B stride = 12-bank rotation). B per tap
// prefetched via cp.async into 2-deep smem ring (272B rows, LDSM2).
// 8 warps = 4(M)x2(N); row r <-> pixel (y0 + r/16, x0 + r%16).
// EPI: 0 = gate + fused LSTM (writes g_c + packed g_rt)
//      1 = planar fp32 out (po)
//      2 = head: h-state + depth output (pout, t)
// ---------------------------------------------------------------------------
template<int KD, int NPAD, int NREAL, int EPI>
__global__ __launch_bounds__(256, 3)
void mma_conv_kernel(const __nv_bfloat16* __restrict__ inpk,
                     const __nv_bfloat16* __restrict__ Bsrc,
                     float* __restrict__ po, float* __restrict__ pout, int t)
{
    constexpr int T    = KD*KD;
    constexpr int PADK = KD/2;
    constexpr int PW   = 16 + KD - 1;
    constexpr int PH   = 8 + KD - 1;
    constexpr int NPIX = PH*PW;
    constexpr int BT   = NPAD/16;
    constexpr int DSTR = NPAD + 5;
    constexpr int PATCH = NPIX*176;
    constexpr int BROW = 272;
    constexpr int BSZ  = NPAD*BROW;

    extern __shared__ __align__(16) char smem[];
    const uint32_t sA  = smem_u32(smem);
    const uint32_t sBB = sA + PATCH;

    const int tid  = threadIdx.x;
    const int lane = tid & 31;
    const int wid  = tid >> 5;
    const int wm   = wid & 3;
    const int wn   = wid >> 2;
    const int mbase = wm*32;
    const int nbase = wn*(NPAD/2);

    const int b   = blockIdx.x / 288;
    const int rem = blockIdx.x - b*288;
    const int ty  = rem / 12, tx = rem - ty*12;
    const int y0  = ty*8,  x0 = tx*16;
    const size_t bpix = (size_t)b * HW;

    // ---- patch fill (once) ----
    {
        const char* base = (const char*)inpk;
        for (int u = tid; u < NPIX*2; u += 256) {
            int pix = u >> 1, half = u & 1;
            int pyy = pix / PW, pxx = pix - pyy*PW;
            int gy = y0 - PADK + pyy, gx = x0 - PADK + pxx;
            uint32_t dst = sA + pix*176 + half*80;
            if ((unsigned)gy < HH && (unsigned)gx < WW) {
                const char* src = base + ((size_t)(bpix + gy*WW + gx))*160 + half*80;
                #pragma unroll
                for (int j = 0; j < 5; ++j) cp16(dst + j*16, src + j*16);
            } else {
                #pragma unroll
                for (int j = 0; j < 5; ++j)
                    *(uint4*)(smem + pix*176 + half*80 + j*16) = make_uint4(0,0,0,0);
            }
        }
        CP_COMMIT();
    }

    // ---- B prefetch for tap 0 ----
    auto copyB = [&](int tp) {
        const char* src = (const char*)Bsrc + (size_t)tp*NPAD*256;
        uint32_t dst = sBB + (uint32_t)(tp & 1)*BSZ;
        #pragma unroll 4
        for (int idx = tid; idx < NPAD*16; idx += 256)
            cp16(dst + (idx >> 4)*BROW + (idx & 15)*16, src + idx*16);
        CP_COMMIT();
    };
    copyB(0);
    CP_WAIT0();
    __syncthreads();

    // per-lane A fragment bases (row r -> pixel (y0 + r/16, x0 + r%16))
    const int r0  = mbase + (lane & 15);
    const int yy  = r0 >> 4, xx = r0 & 15;
    const uint32_t aBase0 = sA + (uint32_t)(((yy + PADK)*PW + xx + PADK)*176)
                          + (uint32_t)((lane >> 4)*16);
    const uint32_t aBase1 = aBase0 + (uint32_t)(PW*176);   // rows +16 => y+1

    float acc[2][BT][4];
    #pragma unroll
    for (int mt = 0; mt < 2; ++mt)
        #pragma unroll
        for (int j = 0; j < BT; ++j)
            #pragma unroll
            for (int q = 0; q < 4; ++q) acc[mt][j][q] = 0.f;

    const int G0[8] = {0, 2, 4, 6, 8, 0, 2, 4};   // A k-group aliasing table

    for (int tap = 0; tap < T; ++tap) {
        // prefetch next B (other buffer; its last readers sync'd at end of tap-1)
        if (tap + 1 < T) { copyB(tap + 1); CP_WAIT1(); }
        else             { CP_WAIT0(); }
        __syncthreads();          // B(tap) visible to all warps

        const int dy = tap / KD - PADK, dx = tap % KD - PADK;
        const uint32_t sh = (uint32_t)((dy*PW + dx)*176);
        const uint32_t bB = sBB + (uint32_t)(tap & 1)*BSZ;
        const uint32_t rbBase = bB + (uint32_t)((nbase + (lane & 7))*BROW)
                              + (uint32_t)((lane >> 3) & 1)*16;
        #pragma unroll
        for (int ks = 0; ks < 8; ++ks) {
            uint32_t a0[4], a1[4];
            const uint32_t off = sh + G0[ks]*16;
            LDSM4(a0, aBase0 + off);
            LDSM4(a1, aBase1 + off);
            #pragma unroll
            for (int j = 0; j < BT; ++j) {
                uint32_t b2[2];
                LDSM2(b2, rbBase + ks*32 + j*8*BROW);
                MMA16816(acc[0][j], a0, b2);
                MMA16816(acc[1][j], a1, b2);
            }
        }
        __syncthreads();          // B(tap) reads done before tap+2 overwrites
    }

    // ---- write D fragments to smem D tile (aliases patch/B region) ----
    {
        float* sD = (float*)smem;
        int r = mbase + (lane >> 2);
        int c0 = nbase + 2*(lane & 3);
        #pragma unroll
        for (int mt = 0; mt < 2; ++mt) {
            #pragma unroll
            for (int j = 0; j < BT; ++j) {
                int rr = r + mt*16, cc = c0 + j*8;
                sD[(rr    )*DSTR + cc    ] = acc[mt][j][0];
                sD[(rr    )*DSTR + cc + 1] = acc[mt][j][1];
                sD[(rr + 8)*DSTR + cc    ] = acc[mt][j][2];
                sD[(rr + 8)*DSTR + cc + 1] = acc[mt][j][3];
            }
        }
    }
    __syncthreads();

    // ---- per-pixel epilogue (threads 0-127, thread = pixel = D row) ----
    if (tid < 128) {
        const float* sD = (const float*)smem + tid*DSTR;
        const int pimg = (y0 + (tid >> 4))*WW + x0 + (tid & 15);
        if (EPI == 0) {
            float v[40];
            float* C = g_c + (size_t)b*8*HW + pimg;
            #pragma unroll
            for (int c = 0; c < 8; ++c) {
                float f  = sigm_(sD[c]      + g_bg[c]);
                float ii = sigm_(sD[8 + c]  + g_bg[8 + c]);
                float gg = tanhf(sD[16 + c] + g_bg[16 + c]);
                float cs = f * C[(size_t)c*HW] + ii * gg;
                C[(size_t)c*HW] = cs;
                v[c] = cs;
            }
            #pragma unroll
            for (int j = 0; j < 32; ++j) v[8+j] = sigm_(sD[24+j] + g_bg[24+j]);
            store_packed(g_rt + (bpix + pimg)*80, v);
        } else if (EPI == 1) {
            float* O = po + (size_t)b*40*HW + pimg;
            #pragma unroll
            for (int c = 0; c < 40; ++c) O[(size_t)c*HW] = sD[c];
        } else {
            float* Hh = g_h + (size_t)b*8*HW + pimg;
            #pragma unroll
            for (int c = 0; c < 8; ++c) Hh[(size_t)c*HW] = sD[c] + g_bh2[c];
            #pragma unroll
            for (int j = 0; j < 3; ++j)
                pout[(((size_t)b*3 + j)*DD + t)*HW + pimg] = sD[8+j] + g_bh2[8+j];
        }
    }
}

// ---------------------------------------------------------------------------
// Host driver
// ---------------------------------------------------------------------------
extern "C" void kernel_launch(void* const* d_in, const int* in_sizes, int n_in,
                              void* d_out, int out_size)
{
    const float* x1  = (const float*)d_in[0];
    const float* x2  = (const float*)d_in[1];
    const float* Wf  = (const float*)d_in[2];
    const float* bf  = (const float*)d_in[3];
    const float* Wi  = (const float*)d_in[4];
    const float* bi  = (const float*)d_in[5];
    const float* Wc  = (const float*)d_in[6];
    const float* bc  = (const float*)d_in[7];
    const float* Wq  = (const float*)d_in[8];
    const float* bq  = (const float*)d_in[9];
    const float* W0  = (const float*)d_in[10];
    const float* g0  = (const float*)d_in[11];
    const float* be0 = (const float*)d_in[12];
    const float* W1  = (const float*)d_in[13];
    const float* g1  = (const float*)d_in[14];
    const float* be1 = (const float*)d_in[15];
    const float* W2  = (const float*)d_in[16];
    const float* b2w = (const float*)d_in[17];
    const float* Wh  = (const float*)d_in[18];
    const float* bh  = (const float*)d_in[19];
    float* out = (float*)d_out;

    float *px0, *px1, *pWg, *pWh2;
    __nv_bfloat16 *pint, *prt, *px0t, *px1t, *pBg, *pB0, *pB1, *pBh;
    cudaGetSymbolAddress((void**)&px0,  g_x0);
    cudaGetSymbolAddress((void**)&px1,  g_x1);
    cudaGetSymbolAddress((void**)&pWg,  g_Wg);
    cudaGetSymbolAddress((void**)&pWh2, g_Wh2);
    cudaGetSymbolAddress((void**)&pint, g_int);
    cudaGetSymbolAddress((void**)&prt,  g_rt);
    cudaGetSymbolAddress((void**)&px0t, g_x0t);
    cudaGetSymbolAddress((void**)&px1t, g_x1t);
    cudaGetSymbolAddress((void**)&pBg,  g_Bg);
    cudaGetSymbolAddress((void**)&pB0,  g_B0);
    cudaGetSymbolAddress((void**)&pB1,  g_B1);
    cudaGetSymbolAddress((void**)&pBh,  g_Bh);

    // dynamic smem: patch + 2 B buffers (D tile aliases patch+B region)
    constexpr int SM_G = 180*176 + 2*64*272;   // 31680 + 34816 = 66496
    constexpr int SM_C = 240*176 + 2*48*272;   // 42240 + 26112 = 68352
    constexpr int SM_H = 240*176 + 2*16*272;   // 42240 +  8704 = 50944
    cudaFuncSetAttribute(mma_conv_kernel<3,64,56,0>,
                         cudaFuncAttributeMaxDynamicSharedMemorySize, SM_G);
    cudaFuncSetAttribute(mma_conv_kernel<5,48,40,1>,
                         cudaFuncAttributeMaxDynamicSharedMemorySize, SM_C);
    cudaFuncSetAttribute(mma_conv_kernel<5,16,11,2>,
                         cudaFuncAttributeMaxDynamicSharedMemorySize, SM_H);

    zero_state_kernel<<<(BB*8*HW + 255)/256, 256>>>();
    prep_weights_kernel<<<(56*40*9 + 255)/256, 256>>>(Wf, bf, Wi, bi, Wc, bc, Wq, bq,
                                                      Wh, bh, W2, b2w);
    prep_B_kernel<<<( 9*64*128 + 255)/256, 256>>>(pWg,  pBg,  9, 64, 56);
    prep_B_kernel<<<(25*48*128 + 255)/256, 256>>>(W0,   pB0, 25, 48, 40);
    prep_B_kernel<<<(25*48*128 + 255)/256, 256>>>(W1,   pB1, 25, 48, 40);
    prep_B_kernel<<<(25*16*128 + 255)/256, 256>>>(pWh2, pBh, 25, 16, 11);

    const size_t O2_OFF = (size_t)BB*3*DD*HW;
    const int NT = 288*BB;              // 1152 tiles (12x * 24y * 4b)
    const int NP = (BB*HW + 255)/256;   // 576 pointwise blocks

    for (int t = 0; t < DD; ++t) {
        for (int phase = 0; phase < 2; ++phase) {
            const float* xin   = phase ? x2 : x1;
            float*       obase = out + (phase ? O2_OFF : 0);

            transform_cat_kernel<<<NP, 256>>>(xin, t, pint);

            // gate conv + fused LSTM -> g_c, packed g_rt
            mma_conv_kernel<3,64,56,0><<<NT, 256, SM_G>>>(pint, pBg, nullptr, nullptr, 0);

            // conv0 -> planar x0
            mma_conv_kernel<5,48,40,1><<<NT, 256, SM_C>>>(prt, pB0, px0, nullptr, 0);
            bn_partial_kernel<<<dim3(40, 8), 256>>>(px0);
            transform_bn_kernel<<<NP, 256>>>(px0, g0, be0, px0t);

            // conv1 -> planar x1
            mma_conv_kernel<5,48,40,1><<<NT, 256, SM_C>>>(px0t, pB1, px1, nullptr, 0);
            bn_partial_kernel<<<dim3(40, 8), 256>>>(px1);
            transform_bn_kernel<<<NP, 256>>>(px1, g1, be1, px1t);

            // head -> h-state + depth output
            mma_conv_kernel<5,16,11,2><<<NT, 256, SM_H>>>(px1t, pBh, nullptr, obase, t);
        }
    }
}